// round 2
// baseline (speedup 1.0000x reference)
#include <cuda_runtime.h>
#include <math.h>

#define N_ENTS 50000
#define N_RELS 500
#define NTOT   50500
#define EMB    256
#define NEDGE  400000
#define BATCH  512
#define BN_EPS 1e-5f

// ---------------- static scratch (no allocations allowed) ----------------
__device__ __align__(16) float g_XRa [(size_t)NTOT * EMB];
__device__ __align__(16) float g_XRb [(size_t)NTOT * EMB];
__device__ __align__(16) float g_S   [(size_t)NTOT * EMB];   // support buffer
__device__ __align__(16) float g_XRrf[(size_t)NTOT * EMB];   // gcn2 output
__device__ __align__(16) float g_Xef [(size_t)N_ENTS * EMB]; // gcn1 output
__device__ __align__(16) float g_hr  [BATCH * EMB];
__device__ __align__(16) float g_hrbn[BATCH * EMB];
__device__ float g_sums[EMB], g_sumsq[EMB], g_scale[EMB], g_bias[EMB];
__device__ __align__(16) float g_HG1T[EMB * EMB];
__device__ __align__(16) float g_HG2T[EMB * EMB];
__device__ __align__(16) float g_HeT [EMB * EMB];
__device__ __align__(16) float g_HrT [EMB * EMB];

// ---------------- weight prep: transposed Hamilton matrices ----------------
// quaternion component table: comp[A][B] = A ^ B ; neg sign bits mask 0x5390
__global__ void build_gcn_ht(const float* __restrict__ W, float* __restrict__ HT) {
    int idx = blockIdx.x * blockDim.x + threadIdx.x;      // 256*256
    int j = idx >> 8, a = idx & 255;                      // HT[j][a] = H[a][j]
    int Bq = j >> 6, t = j & 63, Aq = a >> 6, p = a & 63;
    int comp = Aq ^ Bq;
    float s = ((0x5390 >> (Aq * 4 + Bq)) & 1) ? -1.f : 1.f;
    HT[idx] = s * W[p * 256 + comp * 64 + t];
}

// lin_ents[l] is (128,256); Hlin is (512,256). Xcat permutation folded in:
// Xnew = Xef @ He + Xrf @ Hr,  He row u=(qe*64+w) -> Hlin row 128*qe+w,
//                              Hr row u           -> Hlin row 128*qe+64+w
__global__ void build_lin_ht(const float* __restrict__ Wl,
                             float* __restrict__ HeT, float* __restrict__ HrT) {
    int idx = blockIdx.x * blockDim.x + threadIdx.x;
    int j = idx >> 8, u = idx & 255;
    int Bq = j >> 6, t = j & 63, qe = u >> 6, w = u & 63;
    int comp = qe ^ Bq;
    float s = ((0x5390 >> (qe * 4 + Bq)) & 1) ? -1.f : 1.f;
    HeT[idx] = s * Wl[w        * 256 + comp * 64 + t];
    HrT[idx] = s * Wl[(64 + w) * 256 + comp * 64 + t];
}

// ---------------- NT SGEMM: C(MxN) = A(MxK) * B(NxK)^T ----------------
// EPI: 0 = store, 1 = accumulate into C, 2 = sigmoid then store
template<int EPI>
__global__ void __launch_bounds__(256)
gemm_nt(const float* __restrict__ A, const float* __restrict__ B,
        float* __restrict__ C, int M, int N, int K) {
    __shared__ float As[16][128];
    __shared__ float Bs[16][128];
    int bm = blockIdx.y * 128;
    int bn = blockIdx.x * 128;
    int tid = threadIdx.x;
    int tx = tid & 15, ty = tid >> 4;
    float acc[8][8];
#pragma unroll
    for (int i = 0; i < 8; i++)
#pragma unroll
        for (int j = 0; j < 8; j++) acc[i][j] = 0.f;

    for (int k0 = 0; k0 < K; k0 += 16) {
#pragma unroll
        for (int ld = 0; ld < 2; ld++) {
            int idx = tid + ld * 256;            // 0..511 -> 128 rows x 4 float4
            int row = idx >> 2;
            int kq  = (idx & 3) * 4;
            float4 av = make_float4(0.f, 0.f, 0.f, 0.f);
            int gr = bm + row;
            if (gr < M) av = *(const float4*)(A + (size_t)gr * K + k0 + kq);
            As[kq + 0][row] = av.x; As[kq + 1][row] = av.y;
            As[kq + 2][row] = av.z; As[kq + 3][row] = av.w;
            float4 bv = make_float4(0.f, 0.f, 0.f, 0.f);
            int gc = bn + row;
            if (gc < N) bv = *(const float4*)(B + (size_t)gc * K + k0 + kq);
            Bs[kq + 0][row] = bv.x; Bs[kq + 1][row] = bv.y;
            Bs[kq + 2][row] = bv.z; Bs[kq + 3][row] = bv.w;
        }
        __syncthreads();
#pragma unroll
        for (int k = 0; k < 16; k++) {
            float ra[8], rb[8];
#pragma unroll
            for (int i = 0; i < 8; i++) ra[i] = As[k][ty * 8 + i];
#pragma unroll
            for (int j = 0; j < 8; j++) rb[j] = Bs[k][tx * 8 + j];
#pragma unroll
            for (int i = 0; i < 8; i++)
#pragma unroll
                for (int j = 0; j < 8; j++) acc[i][j] += ra[i] * rb[j];
        }
        __syncthreads();
    }
#pragma unroll
    for (int i = 0; i < 8; i++) {
        int gr = bm + ty * 8 + i;
        if (gr >= M) continue;
#pragma unroll
        for (int j = 0; j < 8; j++) {
            int gc = bn + tx * 8 + j;
            if (gc >= N) continue;
            size_t o = (size_t)gr * N + gc;
            float v = acc[i][j];
            if (EPI == 1) v += C[o];
            if (EPI == 2) v = 1.f / (1.f + expf(-v));
            C[o] = v;
        }
    }
}

// ---------------- segment sum: Agg[rows[e]] += vals[e] * S[cols[e]] ----------------
__global__ void segsum(const int* __restrict__ rows, const int* __restrict__ cols,
                       const float* __restrict__ vals, const float* __restrict__ S,
                       float* __restrict__ Agg, int nE) {
    int w = (blockIdx.x * blockDim.x + threadIdx.x) >> 5;
    int lane = threadIdx.x & 31;
    if (w >= nE) return;
    int r = rows[w], c = cols[w];
    float v = vals[w];
    const float4* src = (const float4*)(S + (size_t)c * EMB);
    float4* dst = (float4*)(Agg + (size_t)r * EMB);
#pragma unroll
    for (int i = 0; i < 2; i++) {
        float4 x = src[lane + 32 * i];
        x.x *= v; x.y *= v; x.z *= v; x.w *= v;
        atomicAdd(dst + lane + 32 * i, x);   // red.global.add.v4.f32 (sm_90+)
    }
}

// ---------------- batchnorm helpers ----------------
__global__ void bn_stats(const float* __restrict__ X, int rows,
                         float* __restrict__ sums, float* __restrict__ sumsq) {
    int col = threadIdx.x;                   // 256 threads
    int nb = gridDim.x;
    int per = (rows + nb - 1) / nb;
    int r0 = blockIdx.x * per;
    int r1 = min(rows, r0 + per);
    float s = 0.f, s2 = 0.f;
    for (int r = r0; r < r1; r++) {
        float v = X[(size_t)r * EMB + col];
        s += v; s2 += v * v;
    }
    atomicAdd(&sums[col], s);
    atomicAdd(&sumsq[col], s2);
}

__global__ void bn_finalize(const float* __restrict__ sums, const float* __restrict__ sumsq,
                            float n, const float* __restrict__ gamma,
                            const float* __restrict__ beta,
                            float* __restrict__ scale, float* __restrict__ bias) {
    int c = threadIdx.x;
    float m = sums[c] / n;
    float var = sumsq[c] / n - m * m;
    float sc = gamma[c] * rsqrtf(var + BN_EPS);
    scale[c] = sc;
    bias[c]  = beta[c] - m * sc;
}

template<bool TANH>
__global__ void bn_apply(const float* __restrict__ X, const float* __restrict__ scale,
                         const float* __restrict__ bias, float* __restrict__ Y, int n4) {
    int i = blockIdx.x * blockDim.x + threadIdx.x;
    if (i >= n4) return;
    float4 x = ((const float4*)X)[i];
    int c = (i & 63) * 4;                    // row stride = 64 float4
    float4 y;
    y.x = x.x * scale[c + 0] + bias[c + 0];
    y.y = x.y * scale[c + 1] + bias[c + 1];
    y.z = x.z * scale[c + 2] + bias[c + 2];
    y.w = x.w * scale[c + 3] + bias[c + 3];
    if (TANH) { y.x = tanhf(y.x); y.y = tanhf(y.y); y.z = tanhf(y.z); y.w = tanhf(y.w); }
    ((float4*)Y)[i] = y;
}

// ---------------- hr = h (x) normalize(p)  (quaternion, per 64-slot) ----------------
__global__ void hr_quat(const int* __restrict__ e1, const int* __restrict__ ridx,
                        const float* __restrict__ X, const float* __restrict__ R,
                        float* __restrict__ hr) {
    int b = blockIdx.x, t = threadIdx.x;     // 512 blocks x 64 threads
    const float* h = X + (size_t)e1[b] * EMB;
    const float* p = R + (size_t)ridx[b] * EMB;
    float pr = p[t], pi = p[64 + t], pj = p[128 + t], pk = p[192 + t];
    float inv = 1.f / sqrtf(pr * pr + pi * pi + pj * pj + pk * pk);
    pr *= inv; pi *= inv; pj *= inv; pk *= inv;
    float hrr = h[t], hi = h[64 + t], hj = h[128 + t], hk = h[192 + t];
    float* o = hr + (size_t)b * EMB;
    o[t]       = hrr * pr - hi * pi - hj * pj - hk * pk;
    o[64 + t]  = hi * pr + hrr * pi - hk * pj + hj * pk;
    o[128 + t] = hj * pr + hk * pi + hrr * pj - hi * pk;
    o[192 + t] = hk * pr - hj * pi + hi * pj + hrr * pk;
}

// ---------------- driver ----------------
extern "C" void kernel_launch(void* const* d_in, const int* in_sizes, int n_in,
                              void* d_out, int out_size) {
    const int*   e1     = (const int*)  d_in[0];
    const int*   ridx   = (const int*)  d_in[1];
    const float* emb    = (const float*)d_in[2];
    const float* gcn1_w = (const float*)d_in[3];
    const float* gcn2_w = (const float*)d_in[4];
    const float* gcn1_g = (const float*)d_in[5];
    const float* gcn1_b = (const float*)d_in[6];
    const float* gcn2_g = (const float*)d_in[7];
    const float* gcn2_b = (const float*)d_in[8];
    const float* lin    = (const float*)d_in[9];
    const float* bns_g  = (const float*)d_in[10];
    const float* bns_b  = (const float*)d_in[11];
    const int*   adj_r  = (const int*)  d_in[12];
    const int*   adj_c  = (const int*)  d_in[13];
    const float* adj_v  = (const float*)d_in[14];
    const int*   adjr_r = (const int*)  d_in[15];
    const int*   adjr_c = (const int*)  d_in[16];
    const float* adjr_v = (const float*)d_in[17];
    float* out = (float*)d_out;

    float *XRa, *XRb, *S, *XRrf, *Xef, *hr, *hrbn, *sums, *sumsq, *scale, *bias;
    float *HG1T, *HG2T, *HeT, *HrT;
    cudaGetSymbolAddress((void**)&XRa,   g_XRa);
    cudaGetSymbolAddress((void**)&XRb,   g_XRb);
    cudaGetSymbolAddress((void**)&S,     g_S);
    cudaGetSymbolAddress((void**)&XRrf,  g_XRrf);
    cudaGetSymbolAddress((void**)&Xef,   g_Xef);
    cudaGetSymbolAddress((void**)&hr,    g_hr);
    cudaGetSymbolAddress((void**)&hrbn,  g_hrbn);
    cudaGetSymbolAddress((void**)&sums,  g_sums);
    cudaGetSymbolAddress((void**)&sumsq, g_sumsq);
    cudaGetSymbolAddress((void**)&scale, g_scale);
    cudaGetSymbolAddress((void**)&bias,  g_bias);
    cudaGetSymbolAddress((void**)&HG1T,  g_HG1T);
    cudaGetSymbolAddress((void**)&HG2T,  g_HG2T);
    cudaGetSymbolAddress((void**)&HeT,   g_HeT);
    cudaGetSymbolAddress((void**)&HrT,   g_HrT);

    auto bn_prep = [&](const float* X, int rows, const float* gamma, const float* beta) {
        cudaMemsetAsync(sums, 0, EMB * sizeof(float));
        cudaMemsetAsync(sumsq, 0, EMB * sizeof(float));
        int grid = rows > 4096 ? 512 : 8;
        bn_stats<<<grid, 256>>>(X, rows, sums, sumsq);
        bn_finalize<<<1, 256>>>(sums, sumsq, (float)rows, gamma, beta, scale, bias);
    };

    auto score = [&](int s, const float* X, const float* R) {
        hr_quat<<<BATCH, 64>>>(e1, ridx, X, R, hr);
        bn_prep(hr, BATCH, bns_g + s * EMB, bns_b + s * EMB);
        int n4 = BATCH * EMB / 4;
        bn_apply<false><<<(n4 + 255) / 256, 256>>>(hr, scale, bias, hrbn, n4);
        dim3 g((N_ENTS + 127) / 128, (BATCH + 127) / 128);
        gemm_nt<2><<<g, 256>>>(hrbn, X, out + (size_t)s * BATCH * N_ENTS,
                               BATCH, N_ENTS, EMB);
    };

    auto q4gnn = [&](const float* Ain, int nrows, const int* er, const int* ec,
                     const float* ev, const float* HT, const float* gamma,
                     const float* beta, float* Aout) {
        dim3 g(2, (nrows + 127) / 128);
        gemm_nt<0><<<g, 256>>>(Ain, HT, S, nrows, EMB, EMB);
        cudaMemsetAsync(Aout, 0, (size_t)nrows * EMB * sizeof(float));
        segsum<<<NEDGE / 8, 256>>>(er, ec, ev, S, Aout, NEDGE);
        bn_prep(Aout, nrows, gamma, beta);
        int n4 = nrows * EMB / 4;
        bn_apply<true><<<(n4 + 255) / 256, 256>>>(Aout, scale, bias, Aout, n4);
    };

    // score 0 on raw embeddings (X = emb[:50000], R = emb[50000:] contiguous)
    score(0, emb, emb + (size_t)N_ENTS * EMB);

    const float* XRcur = emb;
    float* XRbufs[2] = {XRa, XRb};
    for (int l = 0; l < 2; l++) {
        build_gcn_ht<<<256, 256>>>(gcn2_w + (size_t)l * 64 * 256, HG2T);
        build_gcn_ht<<<256, 256>>>(gcn1_w + (size_t)l * 64 * 256, HG1T);
        build_lin_ht<<<256, 256>>>(lin + (size_t)l * 128 * 256, HeT, HrT);

        q4gnn(XRcur, NTOT,   adjr_r, adjr_c, adjr_v, HG2T,
              gcn2_g + l * EMB, gcn2_b + l * EMB, XRrf);
        q4gnn(XRcur, N_ENTS, adj_r,  adj_c,  adj_v,  HG1T,
              gcn1_g + l * EMB, gcn1_b + l * EMB, Xef);

        float* XRnext = XRbufs[l];
        dim3 g(2, (N_ENTS + 127) / 128);
        gemm_nt<0><<<g, 256>>>(Xef,  HeT, XRnext, N_ENTS, EMB, EMB);
        gemm_nt<1><<<g, 256>>>(XRrf, HrT, XRnext, N_ENTS, EMB, EMB);
        cudaMemcpyAsync(XRnext + (size_t)N_ENTS * EMB, XRrf + (size_t)N_ENTS * EMB,
                        (size_t)N_RELS * EMB * sizeof(float), cudaMemcpyDeviceToDevice);

        score(l + 1, XRnext, XRnext + (size_t)N_ENTS * EMB);
        XRcur = XRnext;
    }
}

// round 11
// speedup vs baseline: 1.3542x; 1.3542x over previous
#include <cuda_runtime.h>
#include <math.h>
#include <stdint.h>

#define N_ENTS 50000
#define N_RELS 500
#define NTOT   50500
#define EMB    256
#define NEDGE  400000
#define BATCH  512
#define BN_EPS 1e-5f

// ---------------- static scratch (no allocations allowed) ----------------
__device__ __align__(16) float g_XRa [(size_t)NTOT * EMB];
__device__ __align__(16) float g_XRb [(size_t)NTOT * EMB];
__device__ __align__(16) float g_S   [(size_t)NTOT * EMB];   // support buffer
__device__ __align__(16) float g_XRrf[(size_t)NTOT * EMB];   // gcn2 output
__device__ __align__(16) float g_Xef [(size_t)N_ENTS * EMB]; // gcn1 output
__device__ __align__(16) float g_hr  [BATCH * EMB];
__device__ __align__(16) float g_hrbn[BATCH * EMB];
__device__ float g_sums[EMB], g_sumsq[EMB], g_scale[EMB], g_bias[EMB];
__device__ __align__(16) float g_HG1T[EMB * EMB];
__device__ __align__(16) float g_HG2T[EMB * EMB];
__device__ __align__(16) float g_HeT [EMB * EMB];
__device__ __align__(16) float g_HrT [EMB * EMB];

// ---------------- weight prep: transposed Hamilton matrices ----------------
__global__ void build_gcn_ht(const float* __restrict__ W, float* __restrict__ HT) {
    int idx = blockIdx.x * blockDim.x + threadIdx.x;      // 256*256
    int j = idx >> 8, a = idx & 255;                      // HT[j][a] = H[a][j]
    int Bq = j >> 6, t = j & 63, Aq = a >> 6, p = a & 63;
    int comp = Aq ^ Bq;
    float s = ((0x5390 >> (Aq * 4 + Bq)) & 1) ? -1.f : 1.f;
    HT[idx] = s * W[p * 256 + comp * 64 + t];
}

__global__ void build_lin_ht(const float* __restrict__ Wl,
                             float* __restrict__ HeT, float* __restrict__ HrT) {
    int idx = blockIdx.x * blockDim.x + threadIdx.x;
    int j = idx >> 8, u = idx & 255;
    int Bq = j >> 6, t = j & 63, qe = u >> 6, w = u & 63;
    int comp = qe ^ Bq;
    float s = ((0x5390 >> (qe * 4 + Bq)) & 1) ? -1.f : 1.f;
    HeT[idx] = s * Wl[w        * 256 + comp * 64 + t];
    HrT[idx] = s * Wl[(64 + w) * 256 + comp * 64 + t];
}

// ---------------- TF32 tensor-core helpers ----------------
__device__ __forceinline__ uint32_t f32_to_tf32(float x) {
    uint32_t r;
    asm("cvt.rna.tf32.f32 %0, %1;" : "=r"(r) : "f"(x));
    return r;
}

// split x into hi (tf32) + lo (tf32 of residual): ~22 mantissa bits total
__device__ __forceinline__ void split_tf32(float x, uint32_t& h, uint32_t& l) {
    h = f32_to_tf32(x);
    l = f32_to_tf32(x - __uint_as_float(h));
}

__device__ __forceinline__ void mma_tf32(float* c, const uint32_t* a, const uint32_t* b) {
    asm volatile(
        "mma.sync.aligned.m16n8k8.row.col.f32.tf32.tf32.f32 "
        "{%0,%1,%2,%3}, {%4,%5,%6,%7}, {%8,%9}, {%0,%1,%2,%3};\n"
        : "+f"(c[0]), "+f"(c[1]), "+f"(c[2]), "+f"(c[3])
        : "r"(a[0]), "r"(a[1]), "r"(a[2]), "r"(a[3]), "r"(b[0]), "r"(b[1]));
}

// ---------------- 3xTF32 NT GEMM: C(MxN) = A(MxK) * B(NxK)^T ----------------
// near-fp32 accuracy: A,B split hi/lo, products hh + hl + lh accumulated fp32.
// BM=128, BN=128, BK=16, 256 threads = 8 warps (2m x 4n), warp tile 64x32
// EPI: 0 = store, 1 = accumulate into C, 2 = sigmoid then store
template<int EPI>
__global__ void __launch_bounds__(256)
gemm_tf32x3(const float* __restrict__ A, const float* __restrict__ B,
            float* __restrict__ C, int M, int N, int K) {
    __shared__ uint32_t Ah[128][20];   // [m][k], stride 20 -> conflict-free frags
    __shared__ uint32_t Al[128][20];
    __shared__ uint32_t Bh[128][20];   // [n][k]
    __shared__ uint32_t Bl[128][20];
    const int bm = blockIdx.y * 128;
    const int bn = blockIdx.x * 128;
    const int tid = threadIdx.x;
    const int warp = tid >> 5, lane = tid & 31;
    const int wm = warp >> 2, wn = warp & 3;       // warp tile origin
    const int grp = lane >> 2, thr = lane & 3;     // mma lane decomposition

    float acc[4][4][4];                            // [mtile][ntile][frag]
#pragma unroll
    for (int i = 0; i < 4; i++)
#pragma unroll
        for (int j = 0; j < 4; j++)
#pragma unroll
            for (int q = 0; q < 4; q++) acc[i][j][q] = 0.f;

    for (int k0 = 0; k0 < K; k0 += 16) {
        __syncthreads();
        // 128 rows x 16 k = 512 float4 per matrix / 256 threads = 2 each
#pragma unroll
        for (int p = 0; p < 2; p++) {
            int f   = tid + p * 256;               // 0..511
            int row = f >> 2;
            int kq  = (f & 3) * 4;
            float4 av = make_float4(0.f, 0.f, 0.f, 0.f);
            int gr = bm + row;
            if (gr < M) av = *(const float4*)(A + (size_t)gr * K + k0 + kq);
            split_tf32(av.x, Ah[row][kq + 0], Al[row][kq + 0]);
            split_tf32(av.y, Ah[row][kq + 1], Al[row][kq + 1]);
            split_tf32(av.z, Ah[row][kq + 2], Al[row][kq + 2]);
            split_tf32(av.w, Ah[row][kq + 3], Al[row][kq + 3]);
            float4 bv = make_float4(0.f, 0.f, 0.f, 0.f);
            int gc = bn + row;
            if (gc < N) bv = *(const float4*)(B + (size_t)gc * K + k0 + kq);
            split_tf32(bv.x, Bh[row][kq + 0], Bl[row][kq + 0]);
            split_tf32(bv.y, Bh[row][kq + 1], Bl[row][kq + 1]);
            split_tf32(bv.z, Bh[row][kq + 2], Bl[row][kq + 2]);
            split_tf32(bv.w, Bh[row][kq + 3], Bl[row][kq + 3]);
        }
        __syncthreads();
#pragma unroll
        for (int k8 = 0; k8 < 2; k8++) {
            const int kk = k8 * 8;
            uint32_t ah[4][4], al[4][4];
#pragma unroll
            for (int i = 0; i < 4; i++) {
                int m0 = wm * 64 + i * 16;
                ah[i][0] = Ah[m0 + grp    ][kk + thr    ];
                ah[i][1] = Ah[m0 + grp + 8][kk + thr    ];
                ah[i][2] = Ah[m0 + grp    ][kk + thr + 4];
                ah[i][3] = Ah[m0 + grp + 8][kk + thr + 4];
                al[i][0] = Al[m0 + grp    ][kk + thr    ];
                al[i][1] = Al[m0 + grp + 8][kk + thr    ];
                al[i][2] = Al[m0 + grp    ][kk + thr + 4];
                al[i][3] = Al[m0 + grp + 8][kk + thr + 4];
            }
            uint32_t bh[4][2], bl[4][2];
#pragma unroll
            for (int j = 0; j < 4; j++) {
                int n0 = wn * 32 + j * 8;
                bh[j][0] = Bh[n0 + grp][kk + thr    ];
                bh[j][1] = Bh[n0 + grp][kk + thr + 4];
                bl[j][0] = Bl[n0 + grp][kk + thr    ];
                bl[j][1] = Bl[n0 + grp][kk + thr + 4];
            }
#pragma unroll
            for (int i = 0; i < 4; i++)
#pragma unroll
                for (int j = 0; j < 4; j++) {
                    mma_tf32(acc[i][j], al[i], bh[j]);   // small terms first
                    mma_tf32(acc[i][j], ah[i], bl[j]);
                    mma_tf32(acc[i][j], ah[i], bh[j]);
                }
        }
    }

    // epilogue: c0 at (grp, 2*thr), c1 at (grp, 2*thr+1), c2/c3 at row+8
#pragma unroll
    for (int i = 0; i < 4; i++) {
        int mbase = bm + wm * 64 + i * 16;
#pragma unroll
        for (int j = 0; j < 4; j++) {
            int nbase = bn + wn * 32 + j * 8;
#pragma unroll
            for (int h = 0; h < 2; h++) {            // row half
                int gr = mbase + grp + h * 8;
                if (gr >= M) continue;
#pragma unroll
                for (int q = 0; q < 2; q++) {        // col pair
                    int gc = nbase + thr * 2 + q;
                    if (gc >= N) continue;
                    size_t o = (size_t)gr * N + gc;
                    float v = acc[i][j][h * 2 + q];
                    if (EPI == 1) v += C[o];
                    if (EPI == 2) v = 1.f / (1.f + __expf(-v));
                    C[o] = v;
                }
            }
        }
    }
}

// ---------------- segment sum: Agg[rows[e]] += vals[e] * S[cols[e]] ----------------
__global__ void segsum(const int* __restrict__ rows, const int* __restrict__ cols,
                       const float* __restrict__ vals, const float* __restrict__ S,
                       float* __restrict__ Agg, int nE) {
    int w = (blockIdx.x * blockDim.x + threadIdx.x) >> 5;
    int lane = threadIdx.x & 31;
    if (w >= nE) return;
    int r = rows[w], c = cols[w];
    float v = vals[w];
    const float4* src = (const float4*)(S + (size_t)c * EMB);
    float4* dst = (float4*)(Agg + (size_t)r * EMB);
#pragma unroll
    for (int i = 0; i < 2; i++) {
        float4 x = src[lane + 32 * i];
        x.x *= v; x.y *= v; x.z *= v; x.w *= v;
        atomicAdd(dst + lane + 32 * i, x);   // red.global.add.v4.f32 (sm_90+)
    }
}

// ---------------- batchnorm helpers ----------------
__global__ void bn_stats(const float* __restrict__ X, int rows,
                         float* __restrict__ sums, float* __restrict__ sumsq) {
    int col = threadIdx.x;                   // 256 threads
    int nb = gridDim.x;
    int per = (rows + nb - 1) / nb;
    int r0 = blockIdx.x * per;
    int r1 = min(rows, r0 + per);
    float s = 0.f, s2 = 0.f;
    for (int r = r0; r < r1; r++) {
        float v = X[(size_t)r * EMB + col];
        s += v; s2 += v * v;
    }
    atomicAdd(&sums[col], s);
    atomicAdd(&sumsq[col], s2);
}

__global__ void bn_finalize(const float* __restrict__ sums, const float* __restrict__ sumsq,
                            float n, const float* __restrict__ gamma,
                            const float* __restrict__ beta,
                            float* __restrict__ scale, float* __restrict__ bias) {
    int c = threadIdx.x;
    float m = sums[c] / n;
    float var = sumsq[c] / n - m * m;
    float sc = gamma[c] * rsqrtf(var + BN_EPS);
    scale[c] = sc;
    bias[c]  = beta[c] - m * sc;
}

template<bool TANH>
__global__ void bn_apply(const float* __restrict__ X, const float* __restrict__ scale,
                         const float* __restrict__ bias, float* __restrict__ Y, int n4) {
    int i = blockIdx.x * blockDim.x + threadIdx.x;
    if (i >= n4) return;
    float4 x = ((const float4*)X)[i];
    int c = (i & 63) * 4;                    // row stride = 64 float4
    float4 y;
    y.x = x.x * scale[c + 0] + bias[c + 0];
    y.y = x.y * scale[c + 1] + bias[c + 1];
    y.z = x.z * scale[c + 2] + bias[c + 2];
    y.w = x.w * scale[c + 3] + bias[c + 3];
    if (TANH) { y.x = tanhf(y.x); y.y = tanhf(y.y); y.z = tanhf(y.z); y.w = tanhf(y.w); }
    ((float4*)Y)[i] = y;
}

// ---------------- hr = h (x) normalize(p)  (quaternion, per 64-slot) ----------------
__global__ void hr_quat(const int* __restrict__ e1, const int* __restrict__ ridx,
                        const float* __restrict__ X, const float* __restrict__ R,
                        float* __restrict__ hr) {
    int b = blockIdx.x, t = threadIdx.x;     // 512 blocks x 64 threads
    const float* h = X + (size_t)e1[b] * EMB;
    const float* p = R + (size_t)ridx[b] * EMB;
    float pr = p[t], pi = p[64 + t], pj = p[128 + t], pk = p[192 + t];
    float inv = 1.f / sqrtf(pr * pr + pi * pi + pj * pj + pk * pk);
    pr *= inv; pi *= inv; pj *= inv; pk *= inv;
    float hrr = h[t], hi = h[64 + t], hj = h[128 + t], hk = h[192 + t];
    float* o = hr + (size_t)b * EMB;
    o[t]       = hrr * pr - hi * pi - hj * pj - hk * pk;
    o[64 + t]  = hi * pr + hrr * pi - hk * pj + hj * pk;
    o[128 + t] = hj * pr + hk * pi + hrr * pj - hi * pk;
    o[192 + t] = hk * pr - hj * pi + hi * pj + hrr * pk;
}

// ---------------- driver ----------------
extern "C" void kernel_launch(void* const* d_in, const int* in_sizes, int n_in,
                              void* d_out, int out_size) {
    const int*   e1     = (const int*)  d_in[0];
    const int*   ridx   = (const int*)  d_in[1];
    const float* emb    = (const float*)d_in[2];
    const float* gcn1_w = (const float*)d_in[3];
    const float* gcn2_w = (const float*)d_in[4];
    const float* gcn1_g = (const float*)d_in[5];
    const float* gcn1_b = (const float*)d_in[6];
    const float* gcn2_g = (const float*)d_in[7];
    const float* gcn2_b = (const float*)d_in[8];
    const float* lin    = (const float*)d_in[9];
    const float* bns_g  = (const float*)d_in[10];
    const float* bns_b  = (const float*)d_in[11];
    const int*   adj_r  = (const int*)  d_in[12];
    const int*   adj_c  = (const int*)  d_in[13];
    const float* adj_v  = (const float*)d_in[14];
    const int*   adjr_r = (const int*)  d_in[15];
    const int*   adjr_c = (const int*)  d_in[16];
    const float* adjr_v = (const float*)d_in[17];
    float* out = (float*)d_out;

    float *XRa, *XRb, *S, *XRrf, *Xef, *hr, *hrbn, *sums, *sumsq, *scale, *bias;
    float *HG1T, *HG2T, *HeT, *HrT;
    cudaGetSymbolAddress((void**)&XRa,   g_XRa);
    cudaGetSymbolAddress((void**)&XRb,   g_XRb);
    cudaGetSymbolAddress((void**)&S,     g_S);
    cudaGetSymbolAddress((void**)&XRrf,  g_XRrf);
    cudaGetSymbolAddress((void**)&Xef,   g_Xef);
    cudaGetSymbolAddress((void**)&hr,    g_hr);
    cudaGetSymbolAddress((void**)&hrbn,  g_hrbn);
    cudaGetSymbolAddress((void**)&sums,  g_sums);
    cudaGetSymbolAddress((void**)&sumsq, g_sumsq);
    cudaGetSymbolAddress((void**)&scale, g_scale);
    cudaGetSymbolAddress((void**)&bias,  g_bias);
    cudaGetSymbolAddress((void**)&HG1T,  g_HG1T);
    cudaGetSymbolAddress((void**)&HG2T,  g_HG2T);
    cudaGetSymbolAddress((void**)&HeT,   g_HeT);
    cudaGetSymbolAddress((void**)&HrT,   g_HrT);

    auto bn_prep = [&](const float* X, int rows, const float* gamma, const float* beta) {
        cudaMemsetAsync(sums, 0, EMB * sizeof(float));
        cudaMemsetAsync(sumsq, 0, EMB * sizeof(float));
        int grid = rows > 4096 ? 512 : 8;
        bn_stats<<<grid, 256>>>(X, rows, sums, sumsq);
        bn_finalize<<<1, 256>>>(sums, sumsq, (float)rows, gamma, beta, scale, bias);
    };

    auto score = [&](int s, const float* X, const float* R) {
        hr_quat<<<BATCH, 64>>>(e1, ridx, X, R, hr);
        bn_prep(hr, BATCH, bns_g + s * EMB, bns_b + s * EMB);
        int n4 = BATCH * EMB / 4;
        bn_apply<false><<<(n4 + 255) / 256, 256>>>(hr, scale, bias, hrbn, n4);
        dim3 g((N_ENTS + 127) / 128, (BATCH + 127) / 128);
        gemm_tf32x3<2><<<g, 256>>>(hrbn, X, out + (size_t)s * BATCH * N_ENTS,
                                   BATCH, N_ENTS, EMB);
    };

    auto q4gnn = [&](const float* Ain, int nrows, const int* er, const int* ec,
                     const float* ev, const float* HT, const float* gamma,
                     const float* beta, float* Aout) {
        dim3 g(2, (nrows + 127) / 128);
        gemm_tf32x3<0><<<g, 256>>>(Ain, HT, S, nrows, EMB, EMB);
        cudaMemsetAsync(Aout, 0, (size_t)nrows * EMB * sizeof(float));
        segsum<<<NEDGE / 8, 256>>>(er, ec, ev, S, Aout, NEDGE);
        bn_prep(Aout, nrows, gamma, beta);
        int n4 = nrows * EMB / 4;
        bn_apply<true><<<(n4 + 255) / 256, 256>>>(Aout, scale, bias, Aout, n4);
    };

    // score 0 on raw embeddings (X = emb[:50000], R = emb[50000:] contiguous)
    score(0, emb, emb + (size_t)N_ENTS * EMB);

    const float* XRcur = emb;
    float* XRbufs[2] = {XRa, XRb};
    for (int l = 0; l < 2; l++) {
        build_gcn_ht<<<256, 256>>>(gcn2_w + (size_t)l * 64 * 256, HG2T);
        build_gcn_ht<<<256, 256>>>(gcn1_w + (size_t)l * 64 * 256, HG1T);
        build_lin_ht<<<256, 256>>>(lin + (size_t)l * 128 * 256, HeT, HrT);

        q4gnn(XRcur, NTOT,   adjr_r, adjr_c, adjr_v, HG2T,
              gcn2_g + l * EMB, gcn2_b + l * EMB, XRrf);
        q4gnn(XRcur, N_ENTS, adj_r,  adj_c,  adj_v,  HG1T,
              gcn1_g + l * EMB, gcn1_b + l * EMB, Xef);

        float* XRnext = XRbufs[l];
        dim3 g(2, (N_ENTS + 127) / 128);
        gemm_tf32x3<0><<<g, 256>>>(Xef,  HeT, XRnext, N_ENTS, EMB, EMB);
        gemm_tf32x3<1><<<g, 256>>>(XRrf, HrT, XRnext, N_ENTS, EMB, EMB);
        cudaMemcpyAsync(XRnext + (size_t)N_ENTS * EMB, XRrf + (size_t)N_ENTS * EMB,
                        (size_t)N_RELS * EMB * sizeof(float), cudaMemcpyDeviceToDevice);

        score(l + 1, XRnext, XRnext + (size_t)N_ENTS * EMB);
        XRcur = XRnext;
    }
}